// round 2
// baseline (speedup 1.0000x reference)
#include <cuda_runtime.h>

#define TT 150
#define NB 8
#define VV 2048
#define CC 16
#define LL 64
#define EE 32768
#define NV 16384
#define L3 192

// ---------------- device scratch ----------------
__device__ float g_xe[(size_t)TT * NV * LL];
__device__ float g_agg[(size_t)TT * NV * LL];
__device__ float g_h[NV * LL];
__device__ float g_hd[NV * LL];
__device__ float g_pre[NV * LL];
__device__ float g_Wgdi[LL * L3];
__device__ float g_Wgci[LL * L3];
__device__ int   g_cnt[VV];
__device__ int   g_off[VV + 1];
__device__ int   g_fill[VV];
__device__ int   g_eid[EE];

// ---------------- helpers ----------------
__device__ __forceinline__ float2 ffma2(float2 a, float2 b, float2 c) {
    unsigned long long ua = ((unsigned long long)__float_as_uint(a.y) << 32) | __float_as_uint(a.x);
    unsigned long long ub = ((unsigned long long)__float_as_uint(b.y) << 32) | __float_as_uint(b.x);
    unsigned long long uc = ((unsigned long long)__float_as_uint(c.y) << 32) | __float_as_uint(c.x);
    unsigned long long ud;
    asm("fma.rn.f32x2 %0, %1, %2, %3;" : "=l"(ud) : "l"(ua), "l"(ub), "l"(uc));
    float2 d;
    d.x = __uint_as_float((unsigned)(ud & 0xffffffffu));
    d.y = __uint_as_float((unsigned)(ud >> 32));
    return d;
}

__device__ __forceinline__ float sigf(float x) {
    x = fminf(fmaxf(x, -20.f), 20.f);
    return __fdividef(1.f, 1.f + __expf(-x));
}
__device__ __forceinline__ float tanh_f(float x) {
    x = fminf(fmaxf(x, -10.f), 10.f);
    float e = __expf(-2.f * x);
    return __fdividef(1.f - e, 1.f + e);
}

// ---------------- weight combine: out[64x192] = A[64x64] @ B[64x192] ----------------
__global__ void k_prep(const float* __restrict__ A, const float* __restrict__ B, int which) {
    int idx = blockIdx.x * blockDim.x + threadIdx.x;
    if (idx >= LL * L3) return;
    int k = idx / L3, j = idx - k * L3;
    float acc = 0.f;
    #pragma unroll 8
    for (int m = 0; m < LL; m++) acc = fmaf(A[k * LL + m], B[m * L3 + j], acc);
    (which ? g_Wgci : g_Wgdi)[idx] = acc;
}

// ---------------- CSR build (deterministic: per-segment edge-id sort) ----------------
__global__ void k_csr0() {
    int i = blockIdx.x * blockDim.x + threadIdx.x;
    if (i < VV) { g_cnt[i] = 0; g_fill[i] = 0; }
}
__global__ void k_count(const int* __restrict__ ei) {
    int i = blockIdx.x * blockDim.x + threadIdx.x;
    if (i < EE) atomicAdd(&g_cnt[ei[EE + i]], 1);
}
__global__ void k_scan() {
    if (threadIdx.x == 0 && blockIdx.x == 0) {
        int acc = 0;
        for (int v = 0; v < VV; v++) { g_off[v] = acc; acc += g_cnt[v]; }
        g_off[VV] = acc;
    }
}
__global__ void k_fill(const int* __restrict__ ei) {
    int i = blockIdx.x * blockDim.x + threadIdx.x;
    if (i < EE) {
        int d = ei[EE + i];
        int p = g_off[d] + atomicAdd(&g_fill[d], 1);
        g_eid[p] = i;
    }
}
__global__ void k_sort() {
    int v = blockIdx.x * blockDim.x + threadIdx.x;
    if (v >= VV) return;
    int s = g_off[v], e = g_off[v + 1];
    for (int i = s + 1; i < e; i++) {
        int key = g_eid[i];
        int j = i - 1;
        while (j >= s && g_eid[j] > key) { g_eid[j + 1] = g_eid[j]; j--; }
        g_eid[j + 1] = key;
    }
}

// ---------------- encoder: xe[t][r][l] = sum_c x[r][c][t]*Wenc[c][l] + benc[l] ----------------
__global__ void __launch_bounds__(256) k_enc(const float* __restrict__ x,
                                             const float* __restrict__ Wenc,
                                             const float* __restrict__ benc) {
    __shared__ float sx[CC * TT];
    __shared__ float2 sW[CC * 32];
    __shared__ float2 sb[32];
    int tid = threadIdx.x;
    int r = blockIdx.x;
    for (int i = tid; i < CC * TT; i += 256) sx[i] = x[(size_t)r * CC * TT + i];
    for (int i = tid; i < CC * 32; i += 256) {
        int c = i >> 5, l = i & 31;
        sW[i] = make_float2(Wenc[c * LL + l], Wenc[c * LL + l + 32]);
    }
    if (tid < 32) sb[tid] = make_float2(benc[tid], benc[tid + 32]);
    __syncthreads();
    int wid = tid >> 5, lane = tid & 31;
    for (int t = wid; t < TT; t += 8) {
        float2 acc = sb[lane];
        #pragma unroll
        for (int c = 0; c < CC; c++) {
            float xs = sx[c * TT + t];
            acc = ffma2(make_float2(xs, xs), sW[c * 32 + lane], acc);
        }
        size_t o = ((size_t)t * NV + r) * LL;
        g_xe[o + lane] = acc.x;
        g_xe[o + lane + 32] = acc.y;
    }
}

// ---------------- aggregation: agg[t][r] = sum_e attr[e]*xe[t][n, src[e]] for dst[e]==v ----------------
__global__ void __launch_bounds__(256) k_agg(const int* __restrict__ ei,
                                             const float* __restrict__ attr) {
    int tid = threadIdx.x, wid = tid >> 5, lane = tid & 31;
    int gw = blockIdx.x * 8 + wid, nw = gridDim.x * 8;
    for (int task = gw; task < TT * NV; task += nw) {
        int t = task >> 14;
        int r = task & (NV - 1);
        int v = r & (VV - 1);
        const float* xb = g_xe + ((size_t)t * NV + (r & ~(VV - 1))) * LL;
        int s0 = g_off[v], s1 = g_off[v + 1];
        float a0 = 0.f, a1 = 0.f;
        for (int e = s0; e < s1; e++) {
            int id = g_eid[e];
            int s = ei[id];
            float w = attr[id];
            const float* row = xb + (size_t)s * LL;
            a0 = fmaf(w, row[lane], a0);
            a1 = fmaf(w, row[lane + 32], a1);
        }
        size_t o = (size_t)task * LL;
        g_agg[o + lane] = a0;
        g_agg[o + lane + 32] = a1;
    }
}

__global__ void k_zero_hd() {
    int i = blockIdx.x * blockDim.x + threadIdx.x;
    if (i < NV * LL) g_hd[i] = 0.f;
}
__global__ void k_copyh() {
    int i = blockIdx.x * blockDim.x + threadIdx.x;
    if (i < NV * LL) g_h[i] = g_xe[i];
}

// ---------------- domain GRU step ----------------
__global__ void __launch_bounds__(256) k_dstep(int t, const float* __restrict__ Wh,
                                               const float* __restrict__ bg) {
    extern __shared__ float sm[];
    float2* sWi = (float2*)sm;
    float2* sWh = sWi + LL * 96;
    float2* sb  = sWh + LL * 96;
    int tid = threadIdx.x;
    for (int i = tid; i < LL * 96; i += 256) {
        int k = i / 96, col = i - k * 96, g = col >> 5, l = col & 31;
        sWi[i] = make_float2(g_Wgdi[k * L3 + g * 64 + l], g_Wgdi[k * L3 + g * 64 + l + 32]);
        sWh[i] = make_float2(Wh[k * L3 + g * 64 + l], Wh[k * L3 + g * 64 + l + 32]);
    }
    if (tid < 96) {
        int g = tid >> 5, l = tid & 31;
        sb[tid] = make_float2(bg[g * 64 + l], bg[g * 64 + l + 32]);
    }
    __syncthreads();
    int wid = tid >> 5, lane = tid & 31;
    const float* aggt = g_agg + (size_t)t * NV * LL;
    for (int task = blockIdx.x * 8 + wid; task < NV / 4; task += gridDim.x * 8) {
        int r0 = task << 2;
        float2 h[4], a[4], gi[4][3], gh[4][3];
        #pragma unroll
        for (int i = 0; i < 4; i++) {
            size_t o = (size_t)(r0 + i) * LL + lane;
            h[i] = make_float2(g_hd[o], g_hd[o + 32]);
            a[i] = make_float2(aggt[o], aggt[o + 32]);
            #pragma unroll
            for (int g = 0; g < 3; g++) {
                gi[i][g] = sb[g * 32 + lane];
                gh[i][g] = make_float2(0.f, 0.f);
            }
        }
        #pragma unroll
        for (int half = 0; half < 2; half++) {
            #pragma unroll 8
            for (int kk = 0; kk < 32; kk++) {
                int k = half * 32 + kk;
                float2 hb[4], ab[4];
                #pragma unroll
                for (int i = 0; i < 4; i++) {
                    float hv = __shfl_sync(0xffffffffu, half ? h[i].y : h[i].x, kk);
                    float av = __shfl_sync(0xffffffffu, half ? a[i].y : a[i].x, kk);
                    hb[i] = make_float2(hv, hv);
                    ab[i] = make_float2(av, av);
                }
                #pragma unroll
                for (int g = 0; g < 3; g++) {
                    float2 wi = sWi[k * 96 + g * 32 + lane];
                    float2 wh = sWh[k * 96 + g * 32 + lane];
                    #pragma unroll
                    for (int i = 0; i < 4; i++) {
                        gi[i][g] = ffma2(ab[i], wi, gi[i][g]);
                        gh[i][g] = ffma2(hb[i], wh, gh[i][g]);
                    }
                }
            }
        }
        #pragma unroll
        for (int i = 0; i < 4; i++) {
            float zx = sigf(gi[i][0].x + gh[i][0].x), zy = sigf(gi[i][0].y + gh[i][0].y);
            float rx = sigf(gi[i][1].x + gh[i][1].x), ry = sigf(gi[i][1].y + gh[i][1].y);
            float nx = tanh_f(gi[i][2].x + rx * gh[i][2].x);
            float ny = tanh_f(gi[i][2].y + ry * gh[i][2].y);
            size_t o = (size_t)(r0 + i) * LL + lane;
            g_hd[o] = (1.f - zx) * nx + zx * h[i].x;
            g_hd[o + 32] = (1.f - zy) * ny + zy * h[i].y;
        }
    }
}

// ---------------- z_D + pre_ode: pre = (tanh(hd@Wd1+bd1)@Wd2+bd2) @ W1bot + ob1 ----------------
__global__ void __launch_bounds__(256) k_zd(const float* __restrict__ Wd1, const float* __restrict__ bd1,
                                            const float* __restrict__ Wd2, const float* __restrict__ bd2,
                                            const float* __restrict__ oW1, const float* __restrict__ ob1) {
    extern __shared__ float sm[];
    float2* sA = (float2*)sm;
    float2* sB = sA + 2048;
    float2* sC = sB + 2048;
    float2* b1 = sC + 2048;
    float2* b2 = b1 + 32;
    float2* b3 = b2 + 32;
    int tid = threadIdx.x;
    for (int i = tid; i < 2048; i += 256) {
        int k = i >> 5, l = i & 31;
        sA[i] = make_float2(Wd1[k * 64 + l], Wd1[k * 64 + l + 32]);
        sB[i] = make_float2(Wd2[k * 64 + l], Wd2[k * 64 + l + 32]);
        sC[i] = make_float2(oW1[(64 + k) * 64 + l], oW1[(64 + k) * 64 + l + 32]);
    }
    if (tid < 32) {
        b1[tid] = make_float2(bd1[tid], bd1[tid + 32]);
        b2[tid] = make_float2(bd2[tid], bd2[tid + 32]);
        b3[tid] = make_float2(ob1[tid], ob1[tid + 32]);
    }
    __syncthreads();
    int wid = tid >> 5, lane = tid & 31;
    for (int r = blockIdx.x * 8 + wid; r < NV; r += gridDim.x * 8) {
        size_t o = (size_t)r * LL + lane;
        float2 hd = make_float2(g_hd[o], g_hd[o + 32]);
        float2 u = b1[lane];
        #pragma unroll
        for (int half = 0; half < 2; half++)
            #pragma unroll 8
            for (int kk = 0; kk < 32; kk++) {
                float hv = __shfl_sync(0xffffffffu, half ? hd.y : hd.x, kk);
                u = ffma2(make_float2(hv, hv), sA[(half * 32 + kk) * 32 + lane], u);
            }
        u.x = tanh_f(u.x); u.y = tanh_f(u.y);
        float2 v = b2[lane];
        #pragma unroll
        for (int half = 0; half < 2; half++)
            #pragma unroll 8
            for (int kk = 0; kk < 32; kk++) {
                float uv = __shfl_sync(0xffffffffu, half ? u.y : u.x, kk);
                v = ffma2(make_float2(uv, uv), sB[(half * 32 + kk) * 32 + lane], v);
            }
        float2 p = b3[lane];
        #pragma unroll
        for (int half = 0; half < 2; half++)
            #pragma unroll 8
            for (int kk = 0; kk < 32; kk++) {
                float vv = __shfl_sync(0xffffffffu, half ? v.y : v.x, kk);
                p = ffma2(make_float2(vv, vv), sC[(half * 32 + kk) * 32 + lane], p);
            }
        g_pre[o] = p.x;
        g_pre[o + 32] = p.y;
    }
}

// ---------------- decode t=0 (z[0] = xe[0]) ----------------
__global__ void __launch_bounds__(256) k_dec0(const float* __restrict__ Wdec,
                                              const float* __restrict__ bdec,
                                              float* __restrict__ out) {
    __shared__ float sW[LL * CC];
    __shared__ float sb[CC];
    __shared__ float srow[8 * LL];
    int tid = threadIdx.x;
    for (int i = tid; i < LL * CC; i += 256) sW[i] = Wdec[i];
    if (tid < CC) sb[tid] = bdec[tid];
    __syncthreads();
    int wid = tid >> 5, lane = tid & 31;
    for (int r = blockIdx.x * 8 + wid; r < NV; r += gridDim.x * 8) {
        size_t o = (size_t)r * LL;
        srow[wid * LL + lane] = g_xe[o + lane];
        srow[wid * LL + lane + 32] = g_xe[o + lane + 32];
        __syncwarp();
        int c = lane & 15, hf = lane >> 4;
        float acc0 = 0.f, acc1 = 0.f;
        #pragma unroll
        for (int j = 0; j < 32; j += 2) {
            int l = (hf << 5) + j;
            acc0 = fmaf(srow[wid * LL + l], sW[l * CC + c], acc0);
            acc1 = fmaf(srow[wid * LL + l + 1], sW[(l + 1) * CC + c], acc1);
        }
        float acc = acc0 + acc1;
        acc += __shfl_xor_sync(0xffffffffu, acc, 16);
        if (lane < 16) out[((size_t)r * CC + c) * TT] = acc + sb[c];
        __syncwarp();
    }
}

// ---------------- main step: ODE Euler + GRU + fused decoder ----------------
__global__ void __launch_bounds__(256) k_mstep(int t,
        const float* __restrict__ Wh, const float* __restrict__ bg,
        const float* __restrict__ oW1, const float* __restrict__ oW2,
        const float* __restrict__ ob2,
        const float* __restrict__ Wdec, const float* __restrict__ bdec,
        float* __restrict__ out) {
    extern __shared__ float sm[];
    float2* sWi = (float2*)sm;            // 6144 f2
    float2* sWhp = sWi + 6144;            // 6144 f2
    float2* sW1 = sWhp + 6144;            // 2048 f2
    float2* sW2 = sW1 + 2048;             // 2048 f2
    float*  sWdec = (float*)(sW2 + 2048); // 1024 f
    float2* sbg = (float2*)(sWdec + 1024);// 96 f2
    float2* sb2 = sbg + 96;               // 32 f2
    float*  sbd = (float*)(sb2 + 32);     // 16 f
    float*  srow = sbd + 16;              // 512 f
    int tid = threadIdx.x;
    for (int i = tid; i < 6144; i += 256) {
        int k = i / 96, col = i - k * 96, g = col >> 5, l = col & 31;
        sWi[i]  = make_float2(g_Wgci[k * L3 + g * 64 + l], g_Wgci[k * L3 + g * 64 + l + 32]);
        sWhp[i] = make_float2(Wh[k * L3 + g * 64 + l], Wh[k * L3 + g * 64 + l + 32]);
    }
    for (int i = tid; i < 2048; i += 256) {
        int k = i >> 5, l = i & 31;
        sW1[i] = make_float2(oW1[k * 64 + l], oW1[k * 64 + l + 32]);
        sW2[i] = make_float2(oW2[k * 64 + l], oW2[k * 64 + l + 32]);
    }
    for (int i = tid; i < 1024; i += 256) sWdec[i] = Wdec[i];
    if (tid < 96) {
        int g = tid >> 5, l = tid & 31;
        sbg[tid] = make_float2(bg[g * 64 + l], bg[g * 64 + l + 32]);
    }
    if (tid < 32) sb2[tid] = make_float2(ob2[tid], ob2[tid + 32]);
    if (tid < 16) sbd[tid] = bdec[tid];
    __syncthreads();
    int wid = tid >> 5, lane = tid & 31;
    const float* aggt = g_agg + (size_t)t * NV * LL;
    for (int task = blockIdx.x * 8 + wid; task < NV / 4; task += gridDim.x * 8) {
        int r0 = task << 2;
        float2 h[4], a[4], u[4];
        #pragma unroll
        for (int i = 0; i < 4; i++) {
            size_t o = (size_t)(r0 + i) * LL + lane;
            h[i] = make_float2(g_h[o], g_h[o + 32]);
            a[i] = make_float2(aggt[o], aggt[o + 32]);
            u[i] = make_float2(g_pre[o], g_pre[o + 32]);
        }
        // Phase A: u = pre + h @ W1top, tanh
        #pragma unroll
        for (int half = 0; half < 2; half++)
            #pragma unroll 8
            for (int kk = 0; kk < 32; kk++) {
                float2 w = sW1[(half * 32 + kk) * 32 + lane];
                #pragma unroll
                for (int i = 0; i < 4; i++) {
                    float hv = __shfl_sync(0xffffffffu, half ? h[i].y : h[i].x, kk);
                    u[i] = ffma2(make_float2(hv, hv), w, u[i]);
                }
            }
        #pragma unroll
        for (int i = 0; i < 4; i++) { u[i].x = tanh_f(u[i].x); u[i].y = tanh_f(u[i].y); }
        // Phase B: ho = h + (u @ W2 + b2)
        float2 ho[4];
        {
            float2 d[4];
            #pragma unroll
            for (int i = 0; i < 4; i++) d[i] = sb2[lane];
            #pragma unroll
            for (int half = 0; half < 2; half++)
                #pragma unroll 8
                for (int kk = 0; kk < 32; kk++) {
                    float2 w = sW2[(half * 32 + kk) * 32 + lane];
                    #pragma unroll
                    for (int i = 0; i < 4; i++) {
                        float uv = __shfl_sync(0xffffffffu, half ? u[i].y : u[i].x, kk);
                        d[i] = ffma2(make_float2(uv, uv), w, d[i]);
                    }
                }
            #pragma unroll
            for (int i = 0; i < 4; i++)
                ho[i] = make_float2(h[i].x + d[i].x, h[i].y + d[i].y);
        }
        // Phase C: gi = agg @ Wcomb + bg ; gh = ho @ Wh
        float2 gi[4][3], gh[4][3];
        #pragma unroll
        for (int i = 0; i < 4; i++)
            #pragma unroll
            for (int g = 0; g < 3; g++) {
                gi[i][g] = sbg[g * 32 + lane];
                gh[i][g] = make_float2(0.f, 0.f);
            }
        #pragma unroll
        for (int half = 0; half < 2; half++) {
            #pragma unroll 8
            for (int kk = 0; kk < 32; kk++) {
                int k = half * 32 + kk;
                float2 hb[4], ab[4];
                #pragma unroll
                for (int i = 0; i < 4; i++) {
                    float hv = __shfl_sync(0xffffffffu, half ? ho[i].y : ho[i].x, kk);
                    float av = __shfl_sync(0xffffffffu, half ? a[i].y : a[i].x, kk);
                    hb[i] = make_float2(hv, hv);
                    ab[i] = make_float2(av, av);
                }
                #pragma unroll
                for (int g = 0; g < 3; g++) {
                    float2 wi = sWi[k * 96 + g * 32 + lane];
                    float2 wv = sWhp[k * 96 + g * 32 + lane];
                    #pragma unroll
                    for (int i = 0; i < 4; i++) {
                        gi[i][g] = ffma2(ab[i], wi, gi[i][g]);
                        gh[i][g] = ffma2(hb[i], wv, gh[i][g]);
                    }
                }
            }
        }
        // Gates + store + fused decode
        #pragma unroll
        for (int i = 0; i < 4; i++) {
            float zx = sigf(gi[i][0].x + gh[i][0].x), zy = sigf(gi[i][0].y + gh[i][0].y);
            float rx = sigf(gi[i][1].x + gh[i][1].x), ry = sigf(gi[i][1].y + gh[i][1].y);
            float nx = tanh_f(gi[i][2].x + rx * gh[i][2].x);
            float ny = tanh_f(gi[i][2].y + ry * gh[i][2].y);
            float hnx = (1.f - zx) * nx + zx * ho[i].x;
            float hny = (1.f - zy) * ny + zy * ho[i].y;
            size_t o = (size_t)(r0 + i) * LL + lane;
            g_h[o] = hnx;
            g_h[o + 32] = hny;
            srow[wid * LL + lane] = hnx;
            srow[wid * LL + lane + 32] = hny;
            __syncwarp();
            int c = lane & 15, hf = lane >> 4;
            float acc0 = 0.f, acc1 = 0.f;
            #pragma unroll
            for (int j = 0; j < 32; j += 2) {
                int l = (hf << 5) + j;
                acc0 = fmaf(srow[wid * LL + l], sWdec[l * CC + c], acc0);
                acc1 = fmaf(srow[wid * LL + l + 1], sWdec[(l + 1) * CC + c], acc1);
            }
            float acc = acc0 + acc1;
            acc += __shfl_xor_sync(0xffffffffu, acc, 16);
            if (lane < 16) out[((size_t)(r0 + i) * CC + c) * TT + t] = acc + sbd[c];
            __syncwarp();
        }
    }
}

// ---------------- launcher ----------------
extern "C" void kernel_launch(void* const* d_in, const int* in_sizes, int n_in,
                              void* d_out, int out_size) {
    const float* x    = (const float*)d_in[0];
    const int*   ei   = (const int*)d_in[1];
    const float* attr = (const float*)d_in[2];
    const float* Wenc = (const float*)d_in[3];
    const float* benc = (const float*)d_in[4];
    const float* Wgd  = (const float*)d_in[5];
    const float* gdWi = (const float*)d_in[6];
    const float* gdWh = (const float*)d_in[7];
    const float* gdb  = (const float*)d_in[8];
    const float* Wd1  = (const float*)d_in[9];
    const float* bd1  = (const float*)d_in[10];
    const float* Wd2  = (const float*)d_in[11];
    const float* bd2  = (const float*)d_in[12];
    const float* oW1  = (const float*)d_in[13];
    const float* ob1  = (const float*)d_in[14];
    const float* oW2  = (const float*)d_in[15];
    const float* ob2  = (const float*)d_in[16];
    const float* Wgc  = (const float*)d_in[17];
    const float* gcWi = (const float*)d_in[18];
    const float* gcWh = (const float*)d_in[19];
    const float* gcb  = (const float*)d_in[20];
    const float* Wdec = (const float*)d_in[21];
    const float* bdec = (const float*)d_in[22];
    float* out = (float*)d_out;

    cudaFuncSetAttribute(k_dstep, cudaFuncAttributeMaxDynamicSharedMemorySize, 99072);
    cudaFuncSetAttribute(k_zd,    cudaFuncAttributeMaxDynamicSharedMemorySize, 49920);
    cudaFuncSetAttribute(k_mstep, cudaFuncAttributeMaxDynamicSharedMemorySize, 138304);

    k_prep<<<48, 256>>>(Wgd, gdWi, 0);
    k_prep<<<48, 256>>>(Wgc, gcWi, 1);
    k_csr0<<<8, 256>>>();
    k_count<<<128, 256>>>(ei);
    k_scan<<<1, 32>>>();
    k_fill<<<128, 256>>>(ei);
    k_sort<<<8, 256>>>();
    k_enc<<<NV, 256>>>(x, Wenc, benc);
    k_agg<<<4096, 256>>>(ei, attr);
    k_zero_hd<<<4096, 256>>>();
    for (int t = 0; t < TT; t++)
        k_dstep<<<296, 256, 99072>>>(t, gdWh, gdb);
    k_zd<<<128, 256, 49920>>>(Wd1, bd1, Wd2, bd2, oW1, ob1);
    k_copyh<<<4096, 256>>>();
    k_dec0<<<128, 256>>>(Wdec, bdec, out);
    for (int t = 1; t < TT; t++)
        k_mstep<<<148, 256, 138304>>>(t, gcWh, gcb, oW1, oW2, ob2, Wdec, bdec, out);
}

// round 3
// speedup vs baseline: 1.2415x; 1.2415x over previous
#include <cuda_runtime.h>

#define TT 150
#define VV 2048
#define CC 16
#define LL 64
#define EE 32768
#define NV 16384
#define L3 192

// ---------------- device scratch ----------------
__device__ float g_xe[(size_t)TT * NV * LL];
__device__ float g_agg[(size_t)TT * NV * LL];
__device__ float g_hd[NV * LL];
__device__ float g_pre[NV * LL];
__device__ float g_Wgdi[LL * L3];
__device__ float g_Wgci[LL * L3];
__device__ int   g_cnt[VV];
__device__ int   g_off[VV + 1];
__device__ int   g_fill[VV];
__device__ int   g_eid[EE];

// ---------------- helpers ----------------
__device__ __forceinline__ float2 ffma2(float2 a, float2 b, float2 c) {
    unsigned long long ua = ((unsigned long long)__float_as_uint(a.y) << 32) | __float_as_uint(a.x);
    unsigned long long ub = ((unsigned long long)__float_as_uint(b.y) << 32) | __float_as_uint(b.x);
    unsigned long long uc = ((unsigned long long)__float_as_uint(c.y) << 32) | __float_as_uint(c.x);
    unsigned long long ud;
    asm("fma.rn.f32x2 %0, %1, %2, %3;" : "=l"(ud) : "l"(ua), "l"(ub), "l"(uc));
    float2 d;
    d.x = __uint_as_float((unsigned)(ud & 0xffffffffu));
    d.y = __uint_as_float((unsigned)(ud >> 32));
    return d;
}

__device__ __forceinline__ float sigf(float x) {
    x = fminf(fmaxf(x, -20.f), 20.f);
    return __fdividef(1.f, 1.f + __expf(-x));
}
__device__ __forceinline__ float tanh_f(float x) {
    x = fminf(fmaxf(x, -10.f), 10.f);
    float e = __expf(-2.f * x);
    return __fdividef(1.f - e, 1.f + e);
}

// ---------------- weight combine: out[64x192] = A[64x64] @ B[64x192] ----------------
__global__ void k_prep(const float* __restrict__ A, const float* __restrict__ B, int which) {
    int idx = blockIdx.x * blockDim.x + threadIdx.x;
    if (idx >= LL * L3) return;
    int k = idx / L3, j = idx - k * L3;
    float acc = 0.f;
    #pragma unroll 8
    for (int m = 0; m < LL; m++) acc = fmaf(A[k * LL + m], B[m * L3 + j], acc);
    (which ? g_Wgci : g_Wgdi)[idx] = acc;
}

// ---------------- CSR build (deterministic: per-segment edge-id sort) ----------------
__global__ void k_csr0() {
    int i = blockIdx.x * blockDim.x + threadIdx.x;
    if (i < VV) { g_cnt[i] = 0; g_fill[i] = 0; }
}
__global__ void k_count(const int* __restrict__ ei) {
    int i = blockIdx.x * blockDim.x + threadIdx.x;
    if (i < EE) atomicAdd(&g_cnt[ei[EE + i]], 1);
}
__global__ void k_scan() {
    if (threadIdx.x == 0 && blockIdx.x == 0) {
        int acc = 0;
        for (int v = 0; v < VV; v++) { g_off[v] = acc; acc += g_cnt[v]; }
        g_off[VV] = acc;
    }
}
__global__ void k_fill(const int* __restrict__ ei) {
    int i = blockIdx.x * blockDim.x + threadIdx.x;
    if (i < EE) {
        int d = ei[EE + i];
        int p = g_off[d] + atomicAdd(&g_fill[d], 1);
        g_eid[p] = i;
    }
}
__global__ void k_sort() {
    int v = blockIdx.x * blockDim.x + threadIdx.x;
    if (v >= VV) return;
    int s = g_off[v], e = g_off[v + 1];
    for (int i = s + 1; i < e; i++) {
        int key = g_eid[i];
        int j = i - 1;
        while (j >= s && g_eid[j] > key) { g_eid[j + 1] = g_eid[j]; j--; }
        g_eid[j + 1] = key;
    }
}

// ---------------- encoder ----------------
__global__ void __launch_bounds__(256) k_enc(const float* __restrict__ x,
                                             const float* __restrict__ Wenc,
                                             const float* __restrict__ benc) {
    __shared__ float sx[CC * TT];
    __shared__ float2 sW[CC * 32];
    __shared__ float2 sb[32];
    int tid = threadIdx.x;
    int r = blockIdx.x;
    for (int i = tid; i < CC * TT; i += 256) sx[i] = x[(size_t)r * CC * TT + i];
    for (int i = tid; i < CC * 32; i += 256) {
        int c = i >> 5, l = i & 31;
        sW[i] = make_float2(Wenc[c * LL + l], Wenc[c * LL + l + 32]);
    }
    if (tid < 32) sb[tid] = make_float2(benc[tid], benc[tid + 32]);
    __syncthreads();
    int wid = tid >> 5, lane = tid & 31;
    for (int t = wid; t < TT; t += 8) {
        float2 acc = sb[lane];
        #pragma unroll
        for (int c = 0; c < CC; c++) {
            float xs = sx[c * TT + t];
            acc = ffma2(make_float2(xs, xs), sW[c * 32 + lane], acc);
        }
        size_t o = ((size_t)t * NV + r) * LL;
        g_xe[o + lane] = acc.x;
        g_xe[o + lane + 32] = acc.y;
    }
}

// ---------------- aggregation (float2 vectorized gather) ----------------
__global__ void __launch_bounds__(256) k_agg(const int* __restrict__ ei,
                                             const float* __restrict__ attr) {
    int tid = threadIdx.x, wid = tid >> 5, lane = tid & 31;
    int gw = blockIdx.x * 8 + wid, nw = gridDim.x * 8;
    for (int task = gw; task < TT * NV; task += nw) {
        int t = task >> 14;
        int r = task & (NV - 1);
        int v = r & (VV - 1);
        const float* xb = g_xe + ((size_t)t * NV + (r & ~(VV - 1))) * LL;
        int s0 = g_off[v], s1 = g_off[v + 1];
        float2 acc = make_float2(0.f, 0.f);
        for (int e = s0; e < s1; e++) {
            int id = g_eid[e];
            int s = ei[id];
            float w = attr[id];
            float2 vv = ((const float2*)(xb + (size_t)s * LL))[lane];
            acc = ffma2(make_float2(w, w), vv, acc);
        }
        ((float2*)(g_agg + (size_t)task * LL))[lane] = acc;
    }
}

// ---------------- persistent domain GRU scan (all 150 steps in one kernel) ----------------
__global__ void __launch_bounds__(512) k_scan1(const float* __restrict__ Wh,
                                               const float* __restrict__ bg) {
    extern __shared__ float sm[];
    float2* sWi = (float2*)sm;        // 6144
    float2* sWh = sWi + 6144;         // 6144
    float2* sb  = sWh + 6144;         // 96
    int tid = threadIdx.x;
    for (int i = tid; i < 6144; i += 512) {
        int k = i / 96, col = i - k * 96, g = col >> 5, l = col & 31;
        sWi[i] = make_float2(g_Wgdi[k * L3 + g * 64 + l], g_Wgdi[k * L3 + g * 64 + l + 32]);
        sWh[i] = make_float2(Wh[k * L3 + g * 64 + l], Wh[k * L3 + g * 64 + l + 32]);
    }
    if (tid < 96) {
        int g = tid >> 5, l = tid & 31;
        sb[tid] = make_float2(bg[g * 64 + l], bg[g * 64 + l + 32]);
    }
    __syncthreads();
    int wid = tid >> 5, lane = tid & 31;
    int nwarp = gridDim.x * 16;
    for (int task = blockIdx.x * 16 + wid; task < NV / 4; task += nwarp) {
        int r0 = task << 2;
        float2 h[4], a[4], an[4];
        #pragma unroll
        for (int i = 0; i < 4; i++) {
            h[i] = make_float2(0.f, 0.f);
            size_t o = (size_t)(r0 + i) * LL + lane;
            an[i] = make_float2(g_agg[o], g_agg[o + 32]);
        }
        for (int t = 0; t < TT; t++) {
            #pragma unroll
            for (int i = 0; i < 4; i++) a[i] = an[i];
            if (t < TT - 1) {
                const float* nb = g_agg + ((size_t)(t + 1) * NV + r0) * LL;
                #pragma unroll
                for (int i = 0; i < 4; i++)
                    an[i] = make_float2(nb[i * LL + lane], nb[i * LL + lane + 32]);
            }
            float2 gi[4][3], gh[4][3];
            #pragma unroll
            for (int i = 0; i < 4; i++)
                #pragma unroll
                for (int g = 0; g < 3; g++) {
                    gi[i][g] = sb[g * 32 + lane];
                    gh[i][g] = make_float2(0.f, 0.f);
                }
            #pragma unroll
            for (int half = 0; half < 2; half++) {
                #pragma unroll 8
                for (int kk = 0; kk < 32; kk++) {
                    int k = half * 32 + kk;
                    float2 hb[4], ab[4];
                    #pragma unroll
                    for (int i = 0; i < 4; i++) {
                        float hv = __shfl_sync(0xffffffffu, half ? h[i].y : h[i].x, kk);
                        float av = __shfl_sync(0xffffffffu, half ? a[i].y : a[i].x, kk);
                        hb[i] = make_float2(hv, hv);
                        ab[i] = make_float2(av, av);
                    }
                    #pragma unroll
                    for (int g = 0; g < 3; g++) {
                        float2 wi = sWi[k * 96 + g * 32 + lane];
                        float2 wh = sWh[k * 96 + g * 32 + lane];
                        #pragma unroll
                        for (int i = 0; i < 4; i++) {
                            gi[i][g] = ffma2(ab[i], wi, gi[i][g]);
                            gh[i][g] = ffma2(hb[i], wh, gh[i][g]);
                        }
                    }
                }
            }
            #pragma unroll
            for (int i = 0; i < 4; i++) {
                float zx = sigf(gi[i][0].x + gh[i][0].x), zy = sigf(gi[i][0].y + gh[i][0].y);
                float rx = sigf(gi[i][1].x + gh[i][1].x), ry = sigf(gi[i][1].y + gh[i][1].y);
                float nx = tanh_f(gi[i][2].x + rx * gh[i][2].x);
                float ny = tanh_f(gi[i][2].y + ry * gh[i][2].y);
                h[i].x = (1.f - zx) * nx + zx * h[i].x;
                h[i].y = (1.f - zy) * ny + zy * h[i].y;
            }
        }
        #pragma unroll
        for (int i = 0; i < 4; i++) {
            size_t o = (size_t)(r0 + i) * LL + lane;
            g_hd[o] = h[i].x;
            g_hd[o + 32] = h[i].y;
        }
    }
}

// ---------------- z_D + pre_ode ----------------
__global__ void __launch_bounds__(256) k_zd(const float* __restrict__ Wd1, const float* __restrict__ bd1,
                                            const float* __restrict__ Wd2, const float* __restrict__ bd2,
                                            const float* __restrict__ oW1, const float* __restrict__ ob1) {
    extern __shared__ float sm[];
    float2* sA = (float2*)sm;
    float2* sB = sA + 2048;
    float2* sC = sB + 2048;
    float2* b1 = sC + 2048;
    float2* b2 = b1 + 32;
    float2* b3 = b2 + 32;
    int tid = threadIdx.x;
    for (int i = tid; i < 2048; i += 256) {
        int k = i >> 5, l = i & 31;
        sA[i] = make_float2(Wd1[k * 64 + l], Wd1[k * 64 + l + 32]);
        sB[i] = make_float2(Wd2[k * 64 + l], Wd2[k * 64 + l + 32]);
        sC[i] = make_float2(oW1[(64 + k) * 64 + l], oW1[(64 + k) * 64 + l + 32]);
    }
    if (tid < 32) {
        b1[tid] = make_float2(bd1[tid], bd1[tid + 32]);
        b2[tid] = make_float2(bd2[tid], bd2[tid + 32]);
        b3[tid] = make_float2(ob1[tid], ob1[tid + 32]);
    }
    __syncthreads();
    int wid = tid >> 5, lane = tid & 31;
    for (int r = blockIdx.x * 8 + wid; r < NV; r += gridDim.x * 8) {
        size_t o = (size_t)r * LL + lane;
        float2 hd = make_float2(g_hd[o], g_hd[o + 32]);
        float2 u = b1[lane];
        #pragma unroll
        for (int half = 0; half < 2; half++)
            #pragma unroll 8
            for (int kk = 0; kk < 32; kk++) {
                float hv = __shfl_sync(0xffffffffu, half ? hd.y : hd.x, kk);
                u = ffma2(make_float2(hv, hv), sA[(half * 32 + kk) * 32 + lane], u);
            }
        u.x = tanh_f(u.x); u.y = tanh_f(u.y);
        float2 v = b2[lane];
        #pragma unroll
        for (int half = 0; half < 2; half++)
            #pragma unroll 8
            for (int kk = 0; kk < 32; kk++) {
                float uv = __shfl_sync(0xffffffffu, half ? u.y : u.x, kk);
                v = ffma2(make_float2(uv, uv), sB[(half * 32 + kk) * 32 + lane], v);
            }
        float2 p = b3[lane];
        #pragma unroll
        for (int half = 0; half < 2; half++)
            #pragma unroll 8
            for (int kk = 0; kk < 32; kk++) {
                float vv = __shfl_sync(0xffffffffu, half ? v.y : v.x, kk);
                p = ffma2(make_float2(vv, vv), sC[(half * 32 + kk) * 32 + lane], p);
            }
        g_pre[o] = p.x;
        g_pre[o + 32] = p.y;
    }
}

// ---------------- persistent main scan: t=0 decode + 149x (ODE + GRU + decode) ----------------
__global__ void __launch_bounds__(512) k_scan2(
        const float* __restrict__ Wh, const float* __restrict__ bg,
        const float* __restrict__ oW1, const float* __restrict__ oW2,
        const float* __restrict__ ob2,
        const float* __restrict__ Wdec, const float* __restrict__ bdec,
        float* __restrict__ out) {
    extern __shared__ float sm[];
    float2* sWi  = (float2*)sm;            // 6144 f2
    float2* sWhp = sWi + 6144;             // 6144 f2
    float2* sW1  = sWhp + 6144;            // 2048 f2
    float2* sW2  = sW1 + 2048;             // 2048 f2
    float*  sWdec = (float*)(sW2 + 2048);  // 1024 f
    float2* sbg = (float2*)(sWdec + 1024); // 96 f2
    float2* sb2 = sbg + 96;                // 32 f2
    float*  sbd = (float*)(sb2 + 32);      // 16 f
    float*  srow = sbd + 16;               // 16*64 f
    int tid = threadIdx.x;
    for (int i = tid; i < 6144; i += 512) {
        int k = i / 96, col = i - k * 96, g = col >> 5, l = col & 31;
        sWi[i]  = make_float2(g_Wgci[k * L3 + g * 64 + l], g_Wgci[k * L3 + g * 64 + l + 32]);
        sWhp[i] = make_float2(Wh[k * L3 + g * 64 + l], Wh[k * L3 + g * 64 + l + 32]);
    }
    for (int i = tid; i < 2048; i += 512) {
        int k = i >> 5, l = i & 31;
        sW1[i] = make_float2(oW1[k * 64 + l], oW1[k * 64 + l + 32]);
        sW2[i] = make_float2(oW2[k * 64 + l], oW2[k * 64 + l + 32]);
    }
    for (int i = tid; i < 1024; i += 512) sWdec[i] = Wdec[i];
    if (tid < 96) {
        int g = tid >> 5, l = tid & 31;
        sbg[tid] = make_float2(bg[g * 64 + l], bg[g * 64 + l + 32]);
    }
    if (tid < 32) sb2[tid] = make_float2(ob2[tid], ob2[tid + 32]);
    if (tid < 16) sbd[tid] = bdec[tid];
    __syncthreads();
    int wid = tid >> 5, lane = tid & 31;
    int nwarp = gridDim.x * 16;
    for (int task = blockIdx.x * 16 + wid; task < NV / 4; task += nwarp) {
        int r0 = task << 2;
        float2 h[4], pre[4], a[4], an[4];
        #pragma unroll
        for (int i = 0; i < 4; i++) {
            size_t o = (size_t)(r0 + i) * LL + lane;
            h[i] = make_float2(g_xe[o], g_xe[o + 32]);
            pre[i] = make_float2(g_pre[o], g_pre[o + 32]);
        }
        // decode t=0 from h (= xe[0])
        #pragma unroll
        for (int i = 0; i < 4; i++) {
            srow[wid * LL + lane] = h[i].x;
            srow[wid * LL + lane + 32] = h[i].y;
            __syncwarp();
            int c = lane & 15, hf = lane >> 4;
            float acc0 = 0.f, acc1 = 0.f;
            #pragma unroll
            for (int j = 0; j < 32; j += 2) {
                int l = (hf << 5) + j;
                acc0 = fmaf(srow[wid * LL + l], sWdec[l * CC + c], acc0);
                acc1 = fmaf(srow[wid * LL + l + 1], sWdec[(l + 1) * CC + c], acc1);
            }
            float acc = acc0 + acc1;
            acc += __shfl_xor_sync(0xffffffffu, acc, 16);
            if (lane < 16) out[((size_t)(r0 + i) * CC + c) * TT] = acc + sbd[c];
            __syncwarp();
        }
        // preload agg[t=1]
        {
            const float* nb = g_agg + ((size_t)1 * NV + r0) * LL;
            #pragma unroll
            for (int i = 0; i < 4; i++)
                an[i] = make_float2(nb[i * LL + lane], nb[i * LL + lane + 32]);
        }
        for (int t = 1; t < TT; t++) {
            #pragma unroll
            for (int i = 0; i < 4; i++) a[i] = an[i];
            if (t < TT - 1) {
                const float* nb = g_agg + ((size_t)(t + 1) * NV + r0) * LL;
                #pragma unroll
                for (int i = 0; i < 4; i++)
                    an[i] = make_float2(nb[i * LL + lane], nb[i * LL + lane + 32]);
            }
            // Phase A: u = pre + h @ W1top, tanh
            float2 u[4];
            #pragma unroll
            for (int i = 0; i < 4; i++) u[i] = pre[i];
            #pragma unroll
            for (int half = 0; half < 2; half++)
                #pragma unroll 8
                for (int kk = 0; kk < 32; kk++) {
                    float2 w = sW1[(half * 32 + kk) * 32 + lane];
                    #pragma unroll
                    for (int i = 0; i < 4; i++) {
                        float hv = __shfl_sync(0xffffffffu, half ? h[i].y : h[i].x, kk);
                        u[i] = ffma2(make_float2(hv, hv), w, u[i]);
                    }
                }
            #pragma unroll
            for (int i = 0; i < 4; i++) { u[i].x = tanh_f(u[i].x); u[i].y = tanh_f(u[i].y); }
            // Phase B: ho = h + (u @ W2 + b2)
            float2 ho[4];
            {
                float2 d[4];
                #pragma unroll
                for (int i = 0; i < 4; i++) d[i] = sb2[lane];
                #pragma unroll
                for (int half = 0; half < 2; half++)
                    #pragma unroll 8
                    for (int kk = 0; kk < 32; kk++) {
                        float2 w = sW2[(half * 32 + kk) * 32 + lane];
                        #pragma unroll
                        for (int i = 0; i < 4; i++) {
                            float uv = __shfl_sync(0xffffffffu, half ? u[i].y : u[i].x, kk);
                            d[i] = ffma2(make_float2(uv, uv), w, d[i]);
                        }
                    }
                #pragma unroll
                for (int i = 0; i < 4; i++)
                    ho[i] = make_float2(h[i].x + d[i].x, h[i].y + d[i].y);
            }
            // Phase C: gi = agg @ Wcomb + bg ; gh = ho @ Wh
            float2 gi[4][3], gh[4][3];
            #pragma unroll
            for (int i = 0; i < 4; i++)
                #pragma unroll
                for (int g = 0; g < 3; g++) {
                    gi[i][g] = sbg[g * 32 + lane];
                    gh[i][g] = make_float2(0.f, 0.f);
                }
            #pragma unroll
            for (int half = 0; half < 2; half++) {
                #pragma unroll 8
                for (int kk = 0; kk < 32; kk++) {
                    int k = half * 32 + kk;
                    float2 hb[4], ab[4];
                    #pragma unroll
                    for (int i = 0; i < 4; i++) {
                        float hv = __shfl_sync(0xffffffffu, half ? ho[i].y : ho[i].x, kk);
                        float av = __shfl_sync(0xffffffffu, half ? a[i].y : a[i].x, kk);
                        hb[i] = make_float2(hv, hv);
                        ab[i] = make_float2(av, av);
                    }
                    #pragma unroll
                    for (int g = 0; g < 3; g++) {
                        float2 wi = sWi[k * 96 + g * 32 + lane];
                        float2 wv = sWhp[k * 96 + g * 32 + lane];
                        #pragma unroll
                        for (int i = 0; i < 4; i++) {
                            gi[i][g] = ffma2(ab[i], wi, gi[i][g]);
                            gh[i][g] = ffma2(hb[i], wv, gh[i][g]);
                        }
                    }
                }
            }
            // Gates + fused decode
            #pragma unroll
            for (int i = 0; i < 4; i++) {
                float zx = sigf(gi[i][0].x + gh[i][0].x), zy = sigf(gi[i][0].y + gh[i][0].y);
                float rx = sigf(gi[i][1].x + gh[i][1].x), ry = sigf(gi[i][1].y + gh[i][1].y);
                float nx = tanh_f(gi[i][2].x + rx * gh[i][2].x);
                float ny = tanh_f(gi[i][2].y + ry * gh[i][2].y);
                h[i].x = (1.f - zx) * nx + zx * ho[i].x;
                h[i].y = (1.f - zy) * ny + zy * ho[i].y;
                srow[wid * LL + lane] = h[i].x;
                srow[wid * LL + lane + 32] = h[i].y;
                __syncwarp();
                int c = lane & 15, hf = lane >> 4;
                float acc0 = 0.f, acc1 = 0.f;
                #pragma unroll
                for (int j = 0; j < 32; j += 2) {
                    int l = (hf << 5) + j;
                    acc0 = fmaf(srow[wid * LL + l], sWdec[l * CC + c], acc0);
                    acc1 = fmaf(srow[wid * LL + l + 1], sWdec[(l + 1) * CC + c], acc1);
                }
                float acc = acc0 + acc1;
                acc += __shfl_xor_sync(0xffffffffu, acc, 16);
                if (lane < 16) out[((size_t)(r0 + i) * CC + c) * TT + t] = acc + sbd[c];
                __syncwarp();
            }
        }
    }
}

// ---------------- launcher ----------------
extern "C" void kernel_launch(void* const* d_in, const int* in_sizes, int n_in,
                              void* d_out, int out_size) {
    const float* x    = (const float*)d_in[0];
    const int*   ei   = (const int*)d_in[1];
    const float* attr = (const float*)d_in[2];
    const float* Wenc = (const float*)d_in[3];
    const float* benc = (const float*)d_in[4];
    const float* Wgd  = (const float*)d_in[5];
    const float* gdWi = (const float*)d_in[6];
    const float* gdWh = (const float*)d_in[7];
    const float* gdb  = (const float*)d_in[8];
    const float* Wd1  = (const float*)d_in[9];
    const float* bd1  = (const float*)d_in[10];
    const float* Wd2  = (const float*)d_in[11];
    const float* bd2  = (const float*)d_in[12];
    const float* oW1  = (const float*)d_in[13];
    const float* ob1  = (const float*)d_in[14];
    const float* oW2  = (const float*)d_in[15];
    const float* ob2  = (const float*)d_in[16];
    const float* Wgc  = (const float*)d_in[17];
    const float* gcWi = (const float*)d_in[18];
    const float* gcWh = (const float*)d_in[19];
    const float* gcb  = (const float*)d_in[20];
    const float* Wdec = (const float*)d_in[21];
    const float* bdec = (const float*)d_in[22];
    float* out = (float*)d_out;

    cudaFuncSetAttribute(k_scan1, cudaFuncAttributeMaxDynamicSharedMemorySize, 99072);
    cudaFuncSetAttribute(k_zd,    cudaFuncAttributeMaxDynamicSharedMemorySize, 49920);
    cudaFuncSetAttribute(k_scan2, cudaFuncAttributeMaxDynamicSharedMemorySize, 140352);

    k_prep<<<48, 256>>>(Wgd, gdWi, 0);
    k_prep<<<48, 256>>>(Wgc, gcWi, 1);
    k_csr0<<<8, 256>>>();
    k_count<<<128, 256>>>(ei);
    k_scan<<<1, 32>>>();
    k_fill<<<128, 256>>>(ei);
    k_sort<<<8, 256>>>();
    k_enc<<<NV, 256>>>(x, Wenc, benc);
    k_agg<<<4096, 256>>>(ei, attr);
    k_scan1<<<148, 512, 99072>>>(gdWh, gdb);
    k_zd<<<128, 256, 49920>>>(Wd1, bd1, Wd2, bd2, oW1, ob1);
    k_scan2<<<148, 512, 140352>>>(gcWh, gcb, oW1, oW2, ob2, Wdec, bdec, out);
}